// round 16
// baseline (speedup 1.0000x reference)
#include <cuda_runtime.h>
#include <cuda_fp16.h>
#include <math.h>
#include <stdint.h>

// ---------------------------------------------------------------------------
// SlotAttention. B=32, N=2048, DIN=DOUT=HID=512, S=2, ITERS=3.
// Big GEMM: pure fp16 mma.sync (xh = LN(x) fp16, whi = W fp16).
// R15 change: k/v shadowed in fp16 for the iteration chain (dots/upd traffic
// halves); v is fp16-only (no fp32 copy needed anywhere).
// ---------------------------------------------------------------------------

#define NROWS 65536
#define D 512

// ---- scratch ----
#define OFF_VH    0                        // v fp16: 33.5M halves = 16777216 floats
#define OFF_KH    16777216                 // k fp16: 16777216 floats
#define OFF_ATTN  33554432                 // 32*2*2048
#define OFF_SLN   (OFF_ATTN + 131072)
#define OFF_UPD   (OFF_SLN  + 32768)
#define OFF_GX    (OFF_UPD  + 32768)
#define OFF_GH    (OFF_GX   + 98304)
#define OFF_HNEW  (OFF_GH   + 98304)
#define OFF_HLN   (OFF_HNEW + 32768)
#define OFF_T     (OFF_HLN  + 32768)
#define OFF_WHI   (OFF_T    + 32768)       // 1024x512 fp16 = 262144 floats
#define OFF_XH    (OFF_WHI  + 262144)      // 65536x512 fp16 = 16777216 floats
#define SCRATCH_FLOATS (OFF_XH + 16777216)

__device__ __align__(256) float g_scratch[SCRATCH_FLOATS];

static __device__ __forceinline__ float sigmoidf_(float x) {
    return 1.0f / (1.0f + expf(-x));
}

static __device__ __forceinline__ uint32_t smem_u32(const void* p) {
    uint32_t a;
    asm("{ .reg .u64 t; cvta.to.shared.u64 t, %1; cvt.u32.u64 %0, t; }"
        : "=r"(a) : "l"(p));
    return a;
}
static __device__ __forceinline__ uint32_t h2u(__half2 h) {
    return *reinterpret_cast<uint32_t*>(&h);
}
static __device__ __forceinline__ float2 u2f2(uint32_t u) {
    __half2 h = *reinterpret_cast<__half2*>(&u);
    return __half22float2(h);
}

#define LDSM4(r0, r1, r2, r3, a)                                              \
    asm volatile("ldmatrix.sync.aligned.m8n8.x4.shared.b16 {%0,%1,%2,%3}, [%4];" \
                 : "=r"(r0), "=r"(r1), "=r"(r2), "=r"(r3) : "r"(a))

#define MMA16816H(c, a, b0, b1)                                               \
    asm volatile("mma.sync.aligned.m16n8k16.row.col.f32.f16.f16.f32 "         \
                 "{%0,%1,%2,%3}, {%4,%5,%6,%7}, {%8,%9}, {%0,%1,%2,%3};"      \
                 : "+f"((c)[0]), "+f"((c)[1]), "+f"((c)[2]), "+f"((c)[3])     \
                 : "r"((a)[0]), "r"((a)[1]), "r"((a)[2]), "r"((a)[3]),        \
                   "r"(b0), "r"(b1))

#define CP16(dst, src)                                                        \
    asm volatile("cp.async.cg.shared.global [%0], [%1], 16;"                  \
                 :: "r"(dst), "l"(src))
#define CP_COMMIT() asm volatile("cp.async.commit_group;" ::: "memory")
#define CP_WAIT0()  asm volatile("cp.async.wait_group 0;" ::: "memory")

// ---------------------------------------------------------------------------
// k_prepx: rowstats + LN + fp16 quantize in one pass. 65536 blocks x 128.
// ---------------------------------------------------------------------------
__global__ void k_prepx(const float* __restrict__ x,
                        const float* __restrict__ g, const float* __restrict__ b,
                        __half* __restrict__ xh) {
    int row = blockIdx.x;
    int t = threadIdx.x;
    float4 v = ((const float4*)(x + (size_t)row * D))[t];
    float s  = v.x + v.y + v.z + v.w;
    float s2 = v.x * v.x + v.y * v.y + v.z * v.z + v.w * v.w;
#pragma unroll
    for (int o = 16; o; o >>= 1) {
        s  += __shfl_down_sync(0xffffffffu, s,  o);
        s2 += __shfl_down_sync(0xffffffffu, s2, o);
    }
    __shared__ float ss[4], ss2[4];
    __shared__ float sm, srs;
    if ((t & 31) == 0) { ss[t >> 5] = s; ss2[t >> 5] = s2; }
    __syncthreads();
    if (t == 0) {
        float S  = ss[0] + ss[1] + ss[2] + ss[3];
        float S2 = ss2[0] + ss2[1] + ss2[2] + ss2[3];
        float m   = S * (1.0f / 512.0f);
        float var = S2 * (1.0f / 512.0f) - m * m;
        sm = m; srs = rsqrtf(var + 1e-5f);
    }
    __syncthreads();
    float m = sm, rs = srs;
    float4 gg = ((const float4*)g)[t];
    float4 bb = ((const float4*)b)[t];
    float v0 = (v.x - m) * rs * gg.x + bb.x;
    float v1 = (v.y - m) * rs * gg.y + bb.y;
    float v2 = (v.z - m) * rs * gg.z + bb.z;
    float v3 = (v.w - m) * rs * gg.w + bb.w;
    __half2 p0 = __halves2half2(__float2half_rn(v0), __float2half_rn(v1));
    __half2 p1 = __halves2half2(__float2half_rn(v2), __float2half_rn(v3));
    *(uint2*)(xh + (size_t)row * D + (t << 2)) = make_uint2(h2u(p0), h2u(p1));
}

// ---------------------------------------------------------------------------
// k_prepw: W = [Wk | Wv] -> K-major fp16: Bh[n][k], n in [0,1024).
// ---------------------------------------------------------------------------
__global__ void k_prepw(const float* __restrict__ Wk, const float* __restrict__ Wv,
                        __half* __restrict__ Bh) {
    int idx = blockIdx.x * 256 + threadIdx.x;
    int k = idx >> 10;
    int n = idx & 1023;
    float w = (n < 512) ? Wk[k * 512 + n] : Wv[k * 512 + (n - 512)];
    Bh[(size_t)n * 512 + k] = __float2half_rn(w);
}

// ---------------------------------------------------------------------------
// k_mmagemm: [K|V] = xh @ Bh^T + bias. Pure fp16 GEMM.
// K half: fp32 -> kout (d_out) + fp16 -> khg. V half: fp16 -> vhg only.
// ---------------------------------------------------------------------------
#define PBUF  32768
#define PAHI  0
#define PBHI  16384
#define PTOT  69632

__global__ __launch_bounds__(256, 2)
void k_mmagemm(const __half* __restrict__ Ahg,
               const __half* __restrict__ Bhg,
               const float* __restrict__ bk, const float* __restrict__ bv,
               float* __restrict__ outK,
               __half* __restrict__ Khg, __half* __restrict__ Vhg) {
    extern __shared__ char smraw[];
    char* smb = (char*)((((uintptr_t)smraw) + 1023) & ~(uintptr_t)1023);
    uint32_t sb = smem_u32(smb);
    int tid = threadIdx.x;
    int wid = tid >> 5;
    int lid = tid & 31;
    int n0 = blockIdx.x << 7;
    int m0 = blockIdx.y << 7;

    const int ln = tid >> 1;
    const int kh = (tid & 1) << 5;
    const __half* ahr = Ahg + (size_t)(m0 + ln) * D;
    const __half* bhr = Bhg + (size_t)(n0 + ln) * D;

    const int wm = (wid & 3) << 5;
    const int wn = (wid >> 2) << 6;

    uint32_t aoffA0, aoffA1, aoffB[4];
    {
        uint32_t r0 = (uint32_t)(wm + (lid & 15));
        aoffA0 = (r0 << 7) + ((lid >> 4) << 4);
        uint32_t r1 = r0 + 16;
        aoffA1 = (r1 << 7) + ((lid >> 4) << 4);
#pragma unroll
        for (int gi = 0; gi < 4; ++gi) {
            uint32_t rn = (uint32_t)(wn + (gi << 4) + (lid & 7) + ((lid >> 4) << 3));
            aoffB[gi] = (rn << 7) + (((lid >> 3) & 1) << 4);
        }
    }

    float acc[2][8][4];
#pragma unroll
    for (int i = 0; i < 2; i++)
#pragma unroll
        for (int j = 0; j < 8; j++)
#pragma unroll
            for (int q = 0; q < 4; q++) acc[i][j][q] = 0.f;

    uint4 ra[4];

    auto cpB = [&](int c, int p) {
        const int k0 = c << 6;
#pragma unroll
        for (int j = 0; j < 4; ++j) {
            uint32_t off = (ln << 7) + ((kh + (j << 3)) << 1);
            uint32_t sw = off ^ ((off >> 3) & 0x70);
            CP16(sb + p * PBUF + PBHI + sw, bhr + k0 + kh + (j << 3));
        }
        CP_COMMIT();
    };
    auto ldgA = [&](int c) {
        const int k0 = c << 6;
#pragma unroll
        for (int j = 0; j < 4; ++j)
            ra[j] = *(const uint4*)(ahr + k0 + kh + (j << 3));
    };
    auto stsA = [&](int p) {
#pragma unroll
        for (int j = 0; j < 4; ++j) {
            const int kk = kh + (j << 3);
            uint32_t off0 = (ln << 7) + (kk << 1);
            uint32_t sw0 = off0 ^ ((off0 >> 3) & 0x70);
            *(uint2*)(smb + p * PBUF + PAHI + sw0) = make_uint2(ra[j].x, ra[j].y);
            uint32_t off1 = (ln << 7) + ((kk + 4) << 1);
            uint32_t sw1 = off1 ^ ((off1 >> 3) & 0x70);
            *(uint2*)(smb + p * PBUF + PAHI + sw1) = make_uint2(ra[j].z, ra[j].w);
        }
    };

    auto compute = [&](int p) {
        const uint32_t base = sb + p * PBUF;
#pragma unroll
        for (int s = 0; s < 4; ++s) {
            const uint32_t kb = s << 5;
            uint32_t o0 = aoffA0 + kb, o1 = aoffA1 + kb;
            uint32_t sw0 = o0 ^ ((o0 >> 3) & 0x70);
            uint32_t sw1 = o1 ^ ((o1 >> 3) & 0x70);
            uint32_t ah[2][4], bh[4][4];
            LDSM4(ah[0][0], ah[0][1], ah[0][2], ah[0][3], base + PAHI + sw0);
            LDSM4(ah[1][0], ah[1][1], ah[1][2], ah[1][3], base + PAHI + sw1);
#pragma unroll
            for (int gi = 0; gi < 4; ++gi) {
                uint32_t ob = aoffB[gi] + kb;
                uint32_t swb = ob ^ ((ob >> 3) & 0x70);
                LDSM4(bh[gi][0], bh[gi][1], bh[gi][2], bh[gi][3], base + PBHI + swb);
            }
#pragma unroll
            for (int gi = 0; gi < 4; ++gi)
#pragma unroll
                for (int mt = 0; mt < 2; ++mt) {
                    MMA16816H(acc[mt][gi * 2 + 0], ah[mt], bh[gi][0], bh[gi][1]);
                    MMA16816H(acc[mt][gi * 2 + 1], ah[mt], bh[gi][2], bh[gi][3]);
                }
        }
    };

    // prologue
    ldgA(0);
    cpB(0, 0);
    stsA(0);
    ldgA(1);
    CP_WAIT0();
    __syncthreads();

    for (int c = 0; c < 8; ++c) {
        const int p = c & 1;
        if (c < 7) cpB(c + 1, p ^ 1);
        compute(p);
        if (c < 7) {
            stsA(p ^ 1);
            if (c < 6) ldgA(c + 2);
            CP_WAIT0();
            __syncthreads();
        }
    }
    __syncthreads();

    // epilogue: regs -> smem stage -> gmem
    float* stage = (float*)smb;   // [128][132]
    const int qrow = lid >> 2;
    const int qcol = (lid & 3) << 1;
#pragma unroll
    for (int mt = 0; mt < 2; ++mt) {
#pragma unroll
        for (int nt = 0; nt < 8; ++nt) {
            int r = wm + mt * 16 + qrow;
            int ccol = wn + nt * 8 + qcol;
            *(float2*)&stage[r * 132 + ccol] =
                make_float2(acc[mt][nt][0], acc[mt][nt][1]);
            *(float2*)&stage[(r + 8) * 132 + ccol] =
                make_float2(acc[mt][nt][2], acc[mt][nt][3]);
        }
    }
    __syncthreads();

    {
        int row = tid >> 1;
        int ch = (tid & 1) << 6;
        if (n0 < 512) {
            const float* bias = bk + n0;
            float* outp = outK + n0;
            __half* khp = Khg + n0;
#pragma unroll
            for (int i = 0; i < 16; ++i) {
                int cb = ch + (i << 2);
                float4 o;
                o.x = stage[row * 132 + cb + 0] + bias[cb + 0];
                o.y = stage[row * 132 + cb + 1] + bias[cb + 1];
                o.z = stage[row * 132 + cb + 2] + bias[cb + 2];
                o.w = stage[row * 132 + cb + 3] + bias[cb + 3];
                *(float4*)(outp + (size_t)(m0 + row) * D + cb) = o;
                __half2 h0 = __floats2half2_rn(o.x, o.y);
                __half2 h1 = __floats2half2_rn(o.z, o.w);
                *(uint2*)(khp + (size_t)(m0 + row) * D + cb) =
                    make_uint2(h2u(h0), h2u(h1));
            }
        } else {
            const float* bias = bv + (n0 - 512);
            __half* vhp = Vhg + (n0 - 512);
#pragma unroll
            for (int i = 0; i < 16; ++i) {
                int cb = ch + (i << 2);
                float o0 = stage[row * 132 + cb + 0] + bias[cb + 0];
                float o1 = stage[row * 132 + cb + 1] + bias[cb + 1];
                float o2 = stage[row * 132 + cb + 2] + bias[cb + 2];
                float o3 = stage[row * 132 + cb + 3] + bias[cb + 3];
                __half2 h0 = __floats2half2_rn(o0, o1);
                __half2 h1 = __floats2half2_rn(o2, o3);
                *(uint2*)(vhp + (size_t)(m0 + row) * D + cb) =
                    make_uint2(h2u(h0), h2u(h1));
            }
        }
    }
}

// ---------------------------------------------------------------------------
// LN over 64 rows of 512.
// ---------------------------------------------------------------------------
__global__ void k_ln64(const float* __restrict__ in, const float* __restrict__ g,
                       const float* __restrict__ b, float* __restrict__ out) {
    int r = blockIdx.x, t = threadIdx.x;
    float4 v = ((const float4*)(in + (size_t)r * D))[t];
    float s  = v.x + v.y + v.z + v.w;
    float s2 = v.x * v.x + v.y * v.y + v.z * v.z + v.w * v.w;
#pragma unroll
    for (int o = 16; o; o >>= 1) {
        s  += __shfl_down_sync(0xffffffffu, s,  o);
        s2 += __shfl_down_sync(0xffffffffu, s2, o);
    }
    __shared__ float ss[4], ss2[4];
    __shared__ float sm, srs;
    if ((t & 31) == 0) { ss[t >> 5] = s; ss2[t >> 5] = s2; }
    __syncthreads();
    if (t == 0) {
        float S  = ss[0] + ss[1] + ss[2] + ss[3];
        float S2 = ss2[0] + ss2[1] + ss2[2] + ss2[3];
        float m   = S * (1.0f / 512.0f);
        float var = S2 * (1.0f / 512.0f) - m * m;
        sm = m; srs = rsqrtf(var + 1e-5f);
    }
    __syncthreads();
    float m = sm, rs = srs;
    float4 gg = ((const float4*)g)[t];
    float4 bb = ((const float4*)b)[t];
    float4 o;
    o.x = (v.x - m) * rs * gg.x + bb.x;
    o.y = (v.y - m) * rs * gg.y + bb.y;
    o.z = (v.z - m) * rs * gg.z + bb.z;
    o.w = (v.w - m) * rs * gg.w + bb.w;
    ((float4*)(out + (size_t)r * D))[t] = o;
}

// ---------------------------------------------------------------------------
// Small GEMM with register prefetch; gridDim.y selects (A,W,bias,out) set.
// ---------------------------------------------------------------------------
template <int TRANSW>
__global__ __launch_bounds__(256) void k_gemm64(
    const float* __restrict__ A, const float* __restrict__ A2,
    const float* __restrict__ W, const float* __restrict__ W2,
    const float* __restrict__ bias, const float* __restrict__ bias2,
    const float* __restrict__ resid,
    float* __restrict__ out, float* __restrict__ out2, int ncols, int relu) {
    __shared__ float As[32][64];
    __shared__ float Ws[32][33];
    int tid  = threadIdx.x;
    int col0 = blockIdx.x << 5;
    int ty = tid >> 5, tx = tid & 31;
    int ar0 = tid >> 3, akp = (tid & 7) << 2;

    const float* Ause = blockIdx.y ? A2 : A;
    const float* Wuse = blockIdx.y ? W2 : W;
    const float* buse = blockIdx.y ? bias2 : bias;
    float* outuse = blockIdx.y ? out2 : out;

    float acc[8];
#pragma unroll
    for (int i = 0; i < 8; i++) acc[i] = 0.f;

    int wn = tid >> 3, wkp = (tid & 7) << 2;
    int wk = tid >> 3, wnp = (tid & 7) << 2;

    float4 pa0 = *(const float4*)(Ause + (size_t)ar0 * D + akp);
    float4 pa1 = *(const float4*)(Ause + (size_t)(ar0 + 32) * D + akp);
    float4 pw;
    if (TRANSW)
        pw = *(const float4*)(Wuse + (size_t)(col0 + wn) * D + wkp);
    else
        pw = *(const float4*)(Wuse + (size_t)wk * ncols + col0 + wnp);

    for (int kt = 0; kt < 512; kt += 32) {
        As[akp + 0][ar0] = pa0.x; As[akp + 1][ar0] = pa0.y;
        As[akp + 2][ar0] = pa0.z; As[akp + 3][ar0] = pa0.w;
        As[akp + 0][ar0 + 32] = pa1.x; As[akp + 1][ar0 + 32] = pa1.y;
        As[akp + 2][ar0 + 32] = pa1.z; As[akp + 3][ar0 + 32] = pa1.w;
        if (TRANSW) {
            Ws[wkp + 0][wn] = pw.x; Ws[wkp + 1][wn] = pw.y;
            Ws[wkp + 2][wn] = pw.z; Ws[wkp + 3][wn] = pw.w;
        } else {
            Ws[wk][wnp + 0] = pw.x; Ws[wk][wnp + 1] = pw.y;
            Ws[wk][wnp + 2] = pw.z; Ws[wk][wnp + 3] = pw.w;
        }
        __syncthreads();
        if (kt + 32 < 512) {
            pa0 = *(const float4*)(Ause + (size_t)ar0 * D + kt + 32 + akp);
            pa1 = *(const float4*)(Ause + (size_t)(ar0 + 32) * D + kt + 32 + akp);
            if (TRANSW)
                pw = *(const float4*)(Wuse + (size_t)(col0 + wn) * D + kt + 32 + wkp);
            else
                pw = *(const float4*)(Wuse + (size_t)(kt + 32 + wk) * ncols + col0 + wnp);
        }
#pragma unroll
        for (int kk = 0; kk < 32; kk++) {
            float w = Ws[kk][tx];
            float a[8];
            *(float4*)&a[0] = *(const float4*)&As[kk][ty << 3];
            *(float4*)&a[4] = *(const float4*)&As[kk][(ty << 3) + 4];
#pragma unroll
            for (int r = 0; r < 8; r++) acc[r] += a[r] * w;
        }
        __syncthreads();
    }

    float bvv = buse[col0 + tx];
#pragma unroll
    for (int r = 0; r < 8; r++) {
        int row = (ty << 3) + r;
        float val = acc[r] + bvv;
        if (relu) val = fmaxf(val, 0.f);
        if (resid) val += resid[(size_t)row * D + col0 + tx];
        outuse[(size_t)row * ncols + col0 + tx] = val;
    }
}

// ---------------------------------------------------------------------------
// dots + softmax over the slot axis. k read as fp16 (half traffic).
// ---------------------------------------------------------------------------
__global__ __launch_bounds__(128) void k_dots(const float* __restrict__ q,
                                              const __half* __restrict__ kh,
                                              float* __restrict__ attn_pre) {
    int b = blockIdx.y, j0 = blockIdx.x << 7;
    int t = threadIdx.x;
    __shared__ float qs0[512], qs1[512];
    __shared__ float ks[128][65];
    {
        float4 q0 = ((const float4*)(q + (size_t)(b * 2 + 0) * D))[t];
        float4 q1 = ((const float4*)(q + (size_t)(b * 2 + 1) * D))[t];
        *(float4*)&qs0[t << 2] = q0;
        *(float4*)&qs1[t << 2] = q1;
    }
    float d0 = 0.f, d1 = 0.f;
    const __half* kb = kh + ((size_t)b * 2048 + j0) * D;
    for (int kc = 0; kc < 512; kc += 64) {
        __syncthreads();
#pragma unroll
        for (int i = 0; i < 8; i++) {
            int f = t + (i << 7);
            int j = f >> 3, hp = (f & 7) << 3;   // 8 halves per uint4
            uint4 kv = *(const uint4*)(kb + (size_t)j * D + kc + hp);
            float2 f0 = u2f2(kv.x), f1 = u2f2(kv.y);
            float2 f2 = u2f2(kv.z), f3 = u2f2(kv.w);
            ks[j][hp + 0] = f0.x; ks[j][hp + 1] = f0.y;
            ks[j][hp + 2] = f1.x; ks[j][hp + 3] = f1.y;
            ks[j][hp + 4] = f2.x; ks[j][hp + 5] = f2.y;
            ks[j][hp + 6] = f3.x; ks[j][hp + 7] = f3.y;
        }
        __syncthreads();
#pragma unroll
        for (int kk = 0; kk < 64; kk++) {
            float kv = ks[t][kk];
            d0 += kv * qs0[kc + kk];
            d1 += kv * qs1[kc + kk];
        }
    }
    const float SC = 0.044194173824159216f;
    d0 *= SC; d1 *= SC;
    float mx = fmaxf(d0, d1);
    float e0 = expf(d0 - mx), e1 = expf(d1 - mx);
    float inv = 1.0f / (e0 + e1);
    attn_pre[b * 4096 + (j0 + t)]        = e0 * inv;
    attn_pre[b * 4096 + 2048 + (j0 + t)] = e1 * inv;
}

// ---------------------------------------------------------------------------
// updates = (v^T @ attn_row) / (rowsum + eps); v read as fp16.
// d-tile 0 also writes attn_out.
// ---------------------------------------------------------------------------
__global__ __launch_bounds__(128) void k_upd(const float* __restrict__ attn_pre,
                                             const __half* __restrict__ vh,
                                             float* __restrict__ upd,
                                             float* __restrict__ attn_out) {
    int b = blockIdx.y, d0 = blockIdx.x << 7, t = threadIdx.x;
    const float* a0p = attn_pre + b * 4096;
    const float* a1p = a0p + 2048;
    float s0 = 0.f, s1 = 0.f;
    for (int j = t; j < 2048; j += 128) { s0 += a0p[j]; s1 += a1p[j]; }
#pragma unroll
    for (int o = 16; o; o >>= 1) {
        s0 += __shfl_down_sync(0xffffffffu, s0, o);
        s1 += __shfl_down_sync(0xffffffffu, s1, o);
    }
    __shared__ float r0[4], r1[4];
    if ((t & 31) == 0) { r0[t >> 5] = s0; r1[t >> 5] = s1; }
    __syncthreads();
    float inv0 = 1.0f / (r0[0] + r0[1] + r0[2] + r0[3] + 1e-8f);
    float inv1 = 1.0f / (r1[0] + r1[1] + r1[2] + r1[3] + 1e-8f);

    if (d0 == 0) {
        float* ao0 = attn_out + b * 4096;
        float* ao1 = ao0 + 2048;
        for (int j = t; j < 2048; j += 128) {
            ao0[j] = a0p[j] * inv0;
            ao1[j] = a1p[j] * inv1;
        }
    }

    __shared__ float w0[256], w1[256];
    float acc0 = 0.f, acc1 = 0.f;
    const __half* vb = vh + (size_t)b * 2048 * D + d0 + t;
    for (int jc = 0; jc < 2048; jc += 256) {
        __syncthreads();
        w0[t] = a0p[jc + t]; w0[t + 128] = a0p[jc + t + 128];
        w1[t] = a1p[jc + t]; w1[t + 128] = a1p[jc + t + 128];
        __syncthreads();
#pragma unroll 8
        for (int jj = 0; jj < 256; jj++) {
            float vv = __half2float(vb[(size_t)(jc + jj) * D]);
            acc0 += vv * w0[jj];
            acc1 += vv * w1[jj];
        }
    }
    upd[(size_t)(b * 2 + 0) * D + d0 + t] = acc0 * inv0;
    upd[(size_t)(b * 2 + 1) * D + d0 + t] = acc1 * inv1;
}

// ---------------------------------------------------------------------------
// Fused GRU gates + LayerNorm(h_new). 64 blocks x 128 threads.
// ---------------------------------------------------------------------------
__global__ void k_gruln(const float* __restrict__ gx, const float* __restrict__ gh,
                        const float* __restrict__ slots,
                        const float* __restrict__ g, const float* __restrict__ b,
                        float* __restrict__ hnew, float* __restrict__ hln) {
    int r = blockIdx.x, t = threadIdx.x;
    const float* gxr = gx + (size_t)r * 1536;
    const float* ghr = gh + (size_t)r * 1536;
    float4 xr = ((const float4*)(gxr))[t];
    float4 hr = ((const float4*)(ghr))[t];
    float4 xz = ((const float4*)(gxr + 512))[t];
    float4 hz = ((const float4*)(ghr + 512))[t];
    float4 xn = ((const float4*)(gxr + 1024))[t];
    float4 hn = ((const float4*)(ghr + 1024))[t];
    float4 hp = ((const float4*)(slots + (size_t)r * D))[t];

    float h[4];
    {
        float rg, z, n;
        rg = sigmoidf_(xr.x + hr.x); z = sigmoidf_(xz.x + hz.x);
        n = tanhf(xn.x + rg * hn.x); h[0] = (1.f - z) * n + z * hp.x;
        rg = sigmoidf_(xr.y + hr.y); z = sigmoidf_(xz.y + hz.y);
        n = tanhf(xn.y + rg * hn.y); h[1] = (1.f - z) * n + z * hp.y;
        rg = sigmoidf_(xr.z + hr.z); z = sigmoidf_(xz.z + hz.z);
        n = tanhf(xn.z + rg * hn.z); h[2] = (1.f - z) * n + z * hp.z;
        rg = sigmoidf_(xr.w + hr.w); z = sigmoidf_(xz.w + hz.w);
        n = tanhf(xn.w + rg * hn.w); h[3] = (1.f - z) * n + z * hp.w;
    }
    ((float4*)(hnew + (size_t)r * D))[t] = make_float4(h[0], h[1], h[2], h[3]);

    float s  = h[0] + h[1] + h[2] + h[3];
    float s2 = h[0]*h[0] + h[1]*h[1] + h[2]*h[2] + h[3]*h[3];
#pragma unroll
    for (int o = 16; o; o >>= 1) {
        s  += __shfl_down_sync(0xffffffffu, s,  o);
        s2 += __shfl_down_sync(0xffffffffu, s2, o);
    }
    __shared__ float ss[4], ss2[4];
    __shared__ float sm, srs;
    if ((t & 31) == 0) { ss[t >> 5] = s; ss2[t >> 5] = s2; }
    __syncthreads();
    if (t == 0) {
        float S  = ss[0] + ss[1] + ss[2] + ss[3];
        float S2 = ss2[0] + ss2[1] + ss2[2] + ss2[3];
        float mm  = S * (1.0f / 512.0f);
        float var = S2 * (1.0f / 512.0f) - mm * mm;
        sm = mm; srs = rsqrtf(var + 1e-5f);
    }
    __syncthreads();
    float mm = sm, rs = srs;
    float4 gg = ((const float4*)g)[t];
    float4 bb = ((const float4*)b)[t];
    float4 o;
    o.x = (h[0] - mm) * rs * gg.x + bb.x;
    o.y = (h[1] - mm) * rs * gg.y + bb.y;
    o.z = (h[2] - mm) * rs * gg.z + bb.z;
    o.w = (h[3] - mm) * rs * gg.w + bb.w;
    ((float4*)(hln + (size_t)r * D))[t] = o;
}

// ---------------------------------------------------------------------------
// host
// ---------------------------------------------------------------------------
extern "C" void kernel_launch(void* const* d_in, const int* in_sizes, int n_in,
                              void* d_out, int out_size) {
    (void)in_sizes; (void)n_in; (void)out_size;
    const float* inputs     = (const float*)d_in[0];
    const float* init_slots = (const float*)d_in[1];
    const float* Wq  = (const float*)d_in[2];
    const float* bq  = (const float*)d_in[3];
    const float* Wk  = (const float*)d_in[4];
    const float* bk  = (const float*)d_in[5];
    const float* Wv  = (const float*)d_in[6];
    const float* bv  = (const float*)d_in[7];
    const float* ln_in_g = (const float*)d_in[8];
    const float* ln_in_b = (const float*)d_in[9];
    const float* ln_s_g  = (const float*)d_in[10];
    const float* ln_s_b  = (const float*)d_in[11];
    const float* ln_f_g  = (const float*)d_in[12];
    const float* ln_f_b  = (const float*)d_in[13];
    const float* gru_wih = (const float*)d_in[14];
    const float* gru_whh = (const float*)d_in[15];
    const float* gru_bih = (const float*)d_in[16];
    const float* gru_bhh = (const float*)d_in[17];
    const float* W1 = (const float*)d_in[18];
    const float* b1 = (const float*)d_in[19];
    const float* W2 = (const float*)d_in[20];
    const float* b2 = (const float*)d_in[21];

    float* out      = (float*)d_out;
    float* slots    = out;
    float* qout     = out + 32768;
    float* kout     = out + 65536;
    float* attn_out = out + 65536 + 33554432;

    float* S = nullptr;
    cudaGetSymbolAddress((void**)&S, g_scratch);
    __half* vh  = (__half*)(S + OFF_VH);
    __half* khs = (__half*)(S + OFF_KH);
    float* attn = S + OFF_ATTN;
    float* sln  = S + OFF_SLN;
    float* upd  = S + OFF_UPD;
    float* gx   = S + OFF_GX;
    float* gh   = S + OFF_GH;
    float* hnew = S + OFF_HNEW;
    float* hln  = S + OFF_HLN;
    float* tbuf = S + OFF_T;
    __half* whi = (__half*)(S + OFF_WHI);
    __half* xh  = (__half*)(S + OFF_XH);

    cudaFuncSetAttribute(k_mmagemm, cudaFuncAttributeMaxDynamicSharedMemorySize,
                         PTOT);

    cudaMemcpyAsync(slots, init_slots, 32768 * sizeof(float),
                    cudaMemcpyDeviceToDevice);

    k_prepw<<<2048, 256>>>(Wk, Wv, whi);
    k_prepx<<<NROWS, 128>>>(inputs, ln_in_g, ln_in_b, xh);
    k_mmagemm<<<dim3(8, 512), 256, PTOT>>>(xh, whi, bk, bv, kout, khs, vh);

    for (int it = 0; it < 3; ++it) {
        k_ln64<<<64, 128>>>(slots, ln_s_g, ln_s_b, sln);
        k_gemm64<0><<<dim3(16, 1), 256>>>(sln, sln, Wq, Wq, bq, bq, nullptr,
                                          qout, qout, 512, 0);
        k_dots<<<dim3(16, 32), 128>>>(qout, khs, attn);
        k_upd<<<dim3(4, 32), 128>>>(attn, vh, upd, attn_out);
        k_gemm64<1><<<dim3(48, 2), 256>>>(upd, slots, gru_wih, gru_whh,
                                          gru_bih, gru_bhh, nullptr,
                                          gx, gh, 1536, 0);
        k_gruln<<<64, 128>>>(gx, gh, slots, ln_f_g, ln_f_b, hnew, hln);
        k_gemm64<0><<<dim3(16, 1), 256>>>(hln, hln, W1, W1, b1, b1, nullptr,
                                          tbuf, tbuf, 512, 1);
        k_gemm64<0><<<dim3(16, 1), 256>>>(tbuf, tbuf, W2, W2, b2, b2, hnew,
                                          slots, slots, 512, 0);
    }
}

// round 17
// speedup vs baseline: 1.8081x; 1.8081x over previous
#include <cuda_runtime.h>
#include <cuda_fp16.h>
#include <math.h>
#include <stdint.h>

// ---------------------------------------------------------------------------
// SlotAttention. B=32, N=2048, DIN=DOUT=HID=512, S=2, ITERS=3.
// Big GEMM: pure fp16 mma.sync. k/v shadowed fp16 for the chain.
// R16 change: k_upd split over j (rowsum / 8-way partial / reduce) to kill
// the ~75us/iter latency-bound tail (was 128 blocks x 2048 serial loads).
// ---------------------------------------------------------------------------

#define NROWS 65536
#define D 512

// ---- scratch ----
#define OFF_VH    0                        // v fp16: 16777216 floats
#define OFF_KH    16777216                 // k fp16: 16777216 floats
#define OFF_ATTN  33554432                 // 32*2*2048
#define OFF_SLN   (OFF_ATTN + 131072)
#define OFF_UPD   (OFF_SLN  + 32768)
#define OFF_GX    (OFF_UPD  + 32768)
#define OFF_GH    (OFF_GX   + 98304)
#define OFF_HNEW  (OFF_GH   + 98304)
#define OFF_HLN   (OFF_HNEW + 32768)
#define OFF_T     (OFF_HLN  + 32768)
#define OFF_WHI   (OFF_T    + 32768)       // 1024x512 fp16 = 262144 floats
#define OFF_XH    (OFF_WHI  + 262144)      // 65536x512 fp16 = 16777216 floats
#define OFF_UPDP  (OFF_XH   + 16777216)    // 8*64*512 partials
#define OFF_RINV  (OFF_UPDP + 262144)      // 64
#define SCRATCH_FLOATS (OFF_RINV + 64)

__device__ __align__(256) float g_scratch[SCRATCH_FLOATS];

static __device__ __forceinline__ float sigmoidf_(float x) {
    return 1.0f / (1.0f + expf(-x));
}

static __device__ __forceinline__ uint32_t smem_u32(const void* p) {
    uint32_t a;
    asm("{ .reg .u64 t; cvta.to.shared.u64 t, %1; cvt.u32.u64 %0, t; }"
        : "=r"(a) : "l"(p));
    return a;
}
static __device__ __forceinline__ uint32_t h2u(__half2 h) {
    return *reinterpret_cast<uint32_t*>(&h);
}
static __device__ __forceinline__ float2 u2f2(uint32_t u) {
    __half2 h = *reinterpret_cast<__half2*>(&u);
    return __half22float2(h);
}

#define LDSM4(r0, r1, r2, r3, a)                                              \
    asm volatile("ldmatrix.sync.aligned.m8n8.x4.shared.b16 {%0,%1,%2,%3}, [%4];" \
                 : "=r"(r0), "=r"(r1), "=r"(r2), "=r"(r3) : "r"(a))

#define MMA16816H(c, a, b0, b1)                                               \
    asm volatile("mma.sync.aligned.m16n8k16.row.col.f32.f16.f16.f32 "         \
                 "{%0,%1,%2,%3}, {%4,%5,%6,%7}, {%8,%9}, {%0,%1,%2,%3};"      \
                 : "+f"((c)[0]), "+f"((c)[1]), "+f"((c)[2]), "+f"((c)[3])     \
                 : "r"((a)[0]), "r"((a)[1]), "r"((a)[2]), "r"((a)[3]),        \
                   "r"(b0), "r"(b1))

#define CP16(dst, src)                                                        \
    asm volatile("cp.async.cg.shared.global [%0], [%1], 16;"                  \
                 :: "r"(dst), "l"(src))
#define CP_COMMIT() asm volatile("cp.async.commit_group;" ::: "memory")
#define CP_WAIT0()  asm volatile("cp.async.wait_group 0;" ::: "memory")

// ---------------------------------------------------------------------------
// k_prepx: rowstats + LN + fp16 quantize. 65536 blocks x 128.
// ---------------------------------------------------------------------------
__global__ void k_prepx(const float* __restrict__ x,
                        const float* __restrict__ g, const float* __restrict__ b,
                        __half* __restrict__ xh) {
    int row = blockIdx.x;
    int t = threadIdx.x;
    float4 v = ((const float4*)(x + (size_t)row * D))[t];
    float s  = v.x + v.y + v.z + v.w;
    float s2 = v.x * v.x + v.y * v.y + v.z * v.z + v.w * v.w;
#pragma unroll
    for (int o = 16; o; o >>= 1) {
        s  += __shfl_down_sync(0xffffffffu, s,  o);
        s2 += __shfl_down_sync(0xffffffffu, s2, o);
    }
    __shared__ float ss[4], ss2[4];
    __shared__ float sm, srs;
    if ((t & 31) == 0) { ss[t >> 5] = s; ss2[t >> 5] = s2; }
    __syncthreads();
    if (t == 0) {
        float S  = ss[0] + ss[1] + ss[2] + ss[3];
        float S2 = ss2[0] + ss2[1] + ss2[2] + ss2[3];
        float m   = S * (1.0f / 512.0f);
        float var = S2 * (1.0f / 512.0f) - m * m;
        sm = m; srs = rsqrtf(var + 1e-5f);
    }
    __syncthreads();
    float m = sm, rs = srs;
    float4 gg = ((const float4*)g)[t];
    float4 bb = ((const float4*)b)[t];
    float v0 = (v.x - m) * rs * gg.x + bb.x;
    float v1 = (v.y - m) * rs * gg.y + bb.y;
    float v2 = (v.z - m) * rs * gg.z + bb.z;
    float v3 = (v.w - m) * rs * gg.w + bb.w;
    __half2 p0 = __halves2half2(__float2half_rn(v0), __float2half_rn(v1));
    __half2 p1 = __halves2half2(__float2half_rn(v2), __float2half_rn(v3));
    *(uint2*)(xh + (size_t)row * D + (t << 2)) = make_uint2(h2u(p0), h2u(p1));
}

// ---------------------------------------------------------------------------
// k_prepw
// ---------------------------------------------------------------------------
__global__ void k_prepw(const float* __restrict__ Wk, const float* __restrict__ Wv,
                        __half* __restrict__ Bh) {
    int idx = blockIdx.x * 256 + threadIdx.x;
    int k = idx >> 10;
    int n = idx & 1023;
    float w = (n < 512) ? Wk[k * 512 + n] : Wv[k * 512 + (n - 512)];
    Bh[(size_t)n * 512 + k] = __float2half_rn(w);
}

// ---------------------------------------------------------------------------
// k_mmagemm: [K|V] = xh @ Bh^T + bias. Pure fp16 GEMM.
// ---------------------------------------------------------------------------
#define PBUF  32768
#define PAHI  0
#define PBHI  16384
#define PTOT  69632

__global__ __launch_bounds__(256, 2)
void k_mmagemm(const __half* __restrict__ Ahg,
               const __half* __restrict__ Bhg,
               const float* __restrict__ bk, const float* __restrict__ bv,
               float* __restrict__ outK,
               __half* __restrict__ Khg, __half* __restrict__ Vhg) {
    extern __shared__ char smraw[];
    char* smb = (char*)((((uintptr_t)smraw) + 1023) & ~(uintptr_t)1023);
    uint32_t sb = smem_u32(smb);
    int tid = threadIdx.x;
    int wid = tid >> 5;
    int lid = tid & 31;
    int n0 = blockIdx.x << 7;
    int m0 = blockIdx.y << 7;

    const int ln = tid >> 1;
    const int kh = (tid & 1) << 5;
    const __half* ahr = Ahg + (size_t)(m0 + ln) * D;
    const __half* bhr = Bhg + (size_t)(n0 + ln) * D;

    const int wm = (wid & 3) << 5;
    const int wn = (wid >> 2) << 6;

    uint32_t aoffA0, aoffA1, aoffB[4];
    {
        uint32_t r0 = (uint32_t)(wm + (lid & 15));
        aoffA0 = (r0 << 7) + ((lid >> 4) << 4);
        uint32_t r1 = r0 + 16;
        aoffA1 = (r1 << 7) + ((lid >> 4) << 4);
#pragma unroll
        for (int gi = 0; gi < 4; ++gi) {
            uint32_t rn = (uint32_t)(wn + (gi << 4) + (lid & 7) + ((lid >> 4) << 3));
            aoffB[gi] = (rn << 7) + (((lid >> 3) & 1) << 4);
        }
    }

    float acc[2][8][4];
#pragma unroll
    for (int i = 0; i < 2; i++)
#pragma unroll
        for (int j = 0; j < 8; j++)
#pragma unroll
            for (int q = 0; q < 4; q++) acc[i][j][q] = 0.f;

    uint4 ra[4];

    auto cpB = [&](int c, int p) {
        const int k0 = c << 6;
#pragma unroll
        for (int j = 0; j < 4; ++j) {
            uint32_t off = (ln << 7) + ((kh + (j << 3)) << 1);
            uint32_t sw = off ^ ((off >> 3) & 0x70);
            CP16(sb + p * PBUF + PBHI + sw, bhr + k0 + kh + (j << 3));
        }
        CP_COMMIT();
    };
    auto ldgA = [&](int c) {
        const int k0 = c << 6;
#pragma unroll
        for (int j = 0; j < 4; ++j)
            ra[j] = *(const uint4*)(ahr + k0 + kh + (j << 3));
    };
    auto stsA = [&](int p) {
#pragma unroll
        for (int j = 0; j < 4; ++j) {
            const int kk = kh + (j << 3);
            uint32_t off0 = (ln << 7) + (kk << 1);
            uint32_t sw0 = off0 ^ ((off0 >> 3) & 0x70);
            *(uint2*)(smb + p * PBUF + PAHI + sw0) = make_uint2(ra[j].x, ra[j].y);
            uint32_t off1 = (ln << 7) + ((kk + 4) << 1);
            uint32_t sw1 = off1 ^ ((off1 >> 3) & 0x70);
            *(uint2*)(smb + p * PBUF + PAHI + sw1) = make_uint2(ra[j].z, ra[j].w);
        }
    };

    auto compute = [&](int p) {
        const uint32_t base = sb + p * PBUF;
#pragma unroll
        for (int s = 0; s < 4; ++s) {
            const uint32_t kb = s << 5;
            uint32_t o0 = aoffA0 + kb, o1 = aoffA1 + kb;
            uint32_t sw0 = o0 ^ ((o0 >> 3) & 0x70);
            uint32_t sw1 = o1 ^ ((o1 >> 3) & 0x70);
            uint32_t ah[2][4], bh[4][4];
            LDSM4(ah[0][0], ah[0][1], ah[0][2], ah[0][3], base + PAHI + sw0);
            LDSM4(ah[1][0], ah[1][1], ah[1][2], ah[1][3], base + PAHI + sw1);
#pragma unroll
            for (int gi = 0; gi < 4; ++gi) {
                uint32_t ob = aoffB[gi] + kb;
                uint32_t swb = ob ^ ((ob >> 3) & 0x70);
                LDSM4(bh[gi][0], bh[gi][1], bh[gi][2], bh[gi][3], base + PBHI + swb);
            }
#pragma unroll
            for (int gi = 0; gi < 4; ++gi)
#pragma unroll
                for (int mt = 0; mt < 2; ++mt) {
                    MMA16816H(acc[mt][gi * 2 + 0], ah[mt], bh[gi][0], bh[gi][1]);
                    MMA16816H(acc[mt][gi * 2 + 1], ah[mt], bh[gi][2], bh[gi][3]);
                }
        }
    };

    ldgA(0);
    cpB(0, 0);
    stsA(0);
    ldgA(1);
    CP_WAIT0();
    __syncthreads();

    for (int c = 0; c < 8; ++c) {
        const int p = c & 1;
        if (c < 7) cpB(c + 1, p ^ 1);
        compute(p);
        if (c < 7) {
            stsA(p ^ 1);
            if (c < 6) ldgA(c + 2);
            CP_WAIT0();
            __syncthreads();
        }
    }
    __syncthreads();

    float* stage = (float*)smb;   // [128][132]
    const int qrow = lid >> 2;
    const int qcol = (lid & 3) << 1;
#pragma unroll
    for (int mt = 0; mt < 2; ++mt) {
#pragma unroll
        for (int nt = 0; nt < 8; ++nt) {
            int r = wm + mt * 16 + qrow;
            int ccol = wn + nt * 8 + qcol;
            *(float2*)&stage[r * 132 + ccol] =
                make_float2(acc[mt][nt][0], acc[mt][nt][1]);
            *(float2*)&stage[(r + 8) * 132 + ccol] =
                make_float2(acc[mt][nt][2], acc[mt][nt][3]);
        }
    }
    __syncthreads();

    {
        int row = tid >> 1;
        int ch = (tid & 1) << 6;
        if (n0 < 512) {
            const float* bias = bk + n0;
            float* outp = outK + n0;
            __half* khp = Khg + n0;
#pragma unroll
            for (int i = 0; i < 16; ++i) {
                int cb = ch + (i << 2);
                float4 o;
                o.x = stage[row * 132 + cb + 0] + bias[cb + 0];
                o.y = stage[row * 132 + cb + 1] + bias[cb + 1];
                o.z = stage[row * 132 + cb + 2] + bias[cb + 2];
                o.w = stage[row * 132 + cb + 3] + bias[cb + 3];
                *(float4*)(outp + (size_t)(m0 + row) * D + cb) = o;
                __half2 h0 = __floats2half2_rn(o.x, o.y);
                __half2 h1 = __floats2half2_rn(o.z, o.w);
                *(uint2*)(khp + (size_t)(m0 + row) * D + cb) =
                    make_uint2(h2u(h0), h2u(h1));
            }
        } else {
            const float* bias = bv + (n0 - 512);
            __half* vhp = Vhg + (n0 - 512);
#pragma unroll
            for (int i = 0; i < 16; ++i) {
                int cb = ch + (i << 2);
                float o0 = stage[row * 132 + cb + 0] + bias[cb + 0];
                float o1 = stage[row * 132 + cb + 1] + bias[cb + 1];
                float o2 = stage[row * 132 + cb + 2] + bias[cb + 2];
                float o3 = stage[row * 132 + cb + 3] + bias[cb + 3];
                __half2 h0 = __floats2half2_rn(o0, o1);
                __half2 h1 = __floats2half2_rn(o2, o3);
                *(uint2*)(vhp + (size_t)(m0 + row) * D + cb) =
                    make_uint2(h2u(h0), h2u(h1));
            }
        }
    }
}

// ---------------------------------------------------------------------------
// LN over 64 rows of 512.
// ---------------------------------------------------------------------------
__global__ void k_ln64(const float* __restrict__ in, const float* __restrict__ g,
                       const float* __restrict__ b, float* __restrict__ out) {
    int r = blockIdx.x, t = threadIdx.x;
    float4 v = ((const float4*)(in + (size_t)r * D))[t];
    float s  = v.x + v.y + v.z + v.w;
    float s2 = v.x * v.x + v.y * v.y + v.z * v.z + v.w * v.w;
#pragma unroll
    for (int o = 16; o; o >>= 1) {
        s  += __shfl_down_sync(0xffffffffu, s,  o);
        s2 += __shfl_down_sync(0xffffffffu, s2, o);
    }
    __shared__ float ss[4], ss2[4];
    __shared__ float sm, srs;
    if ((t & 31) == 0) { ss[t >> 5] = s; ss2[t >> 5] = s2; }
    __syncthreads();
    if (t == 0) {
        float S  = ss[0] + ss[1] + ss[2] + ss[3];
        float S2 = ss2[0] + ss2[1] + ss2[2] + ss2[3];
        float m   = S * (1.0f / 512.0f);
        float var = S2 * (1.0f / 512.0f) - m * m;
        sm = m; srs = rsqrtf(var + 1e-5f);
    }
    __syncthreads();
    float m = sm, rs = srs;
    float4 gg = ((const float4*)g)[t];
    float4 bb = ((const float4*)b)[t];
    float4 o;
    o.x = (v.x - m) * rs * gg.x + bb.x;
    o.y = (v.y - m) * rs * gg.y + bb.y;
    o.z = (v.z - m) * rs * gg.z + bb.z;
    o.w = (v.w - m) * rs * gg.w + bb.w;
    ((float4*)(out + (size_t)r * D))[t] = o;
}

// ---------------------------------------------------------------------------
// Small GEMM with register prefetch; gridDim.y selects (A,W,bias,out) set.
// ---------------------------------------------------------------------------
template <int TRANSW>
__global__ __launch_bounds__(256) void k_gemm64(
    const float* __restrict__ A, const float* __restrict__ A2,
    const float* __restrict__ W, const float* __restrict__ W2,
    const float* __restrict__ bias, const float* __restrict__ bias2,
    const float* __restrict__ resid,
    float* __restrict__ out, float* __restrict__ out2, int ncols, int relu) {
    __shared__ float As[32][64];
    __shared__ float Ws[32][33];
    int tid  = threadIdx.x;
    int col0 = blockIdx.x << 5;
    int ty = tid >> 5, tx = tid & 31;
    int ar0 = tid >> 3, akp = (tid & 7) << 2;

    const float* Ause = blockIdx.y ? A2 : A;
    const float* Wuse = blockIdx.y ? W2 : W;
    const float* buse = blockIdx.y ? bias2 : bias;
    float* outuse = blockIdx.y ? out2 : out;

    float acc[8];
#pragma unroll
    for (int i = 0; i < 8; i++) acc[i] = 0.f;

    int wn = tid >> 3, wkp = (tid & 7) << 2;
    int wk = tid >> 3, wnp = (tid & 7) << 2;

    float4 pa0 = *(const float4*)(Ause + (size_t)ar0 * D + akp);
    float4 pa1 = *(const float4*)(Ause + (size_t)(ar0 + 32) * D + akp);
    float4 pw;
    if (TRANSW)
        pw = *(const float4*)(Wuse + (size_t)(col0 + wn) * D + wkp);
    else
        pw = *(const float4*)(Wuse + (size_t)wk * ncols + col0 + wnp);

    for (int kt = 0; kt < 512; kt += 32) {
        As[akp + 0][ar0] = pa0.x; As[akp + 1][ar0] = pa0.y;
        As[akp + 2][ar0] = pa0.z; As[akp + 3][ar0] = pa0.w;
        As[akp + 0][ar0 + 32] = pa1.x; As[akp + 1][ar0 + 32] = pa1.y;
        As[akp + 2][ar0 + 32] = pa1.z; As[akp + 3][ar0 + 32] = pa1.w;
        if (TRANSW) {
            Ws[wkp + 0][wn] = pw.x; Ws[wkp + 1][wn] = pw.y;
            Ws[wkp + 2][wn] = pw.z; Ws[wkp + 3][wn] = pw.w;
        } else {
            Ws[wk][wnp + 0] = pw.x; Ws[wk][wnp + 1] = pw.y;
            Ws[wk][wnp + 2] = pw.z; Ws[wk][wnp + 3] = pw.w;
        }
        __syncthreads();
        if (kt + 32 < 512) {
            pa0 = *(const float4*)(Ause + (size_t)ar0 * D + kt + 32 + akp);
            pa1 = *(const float4*)(Ause + (size_t)(ar0 + 32) * D + kt + 32 + akp);
            if (TRANSW)
                pw = *(const float4*)(Wuse + (size_t)(col0 + wn) * D + kt + 32 + wkp);
            else
                pw = *(const float4*)(Wuse + (size_t)(kt + 32 + wk) * ncols + col0 + wnp);
        }
#pragma unroll
        for (int kk = 0; kk < 32; kk++) {
            float w = Ws[kk][tx];
            float a[8];
            *(float4*)&a[0] = *(const float4*)&As[kk][ty << 3];
            *(float4*)&a[4] = *(const float4*)&As[kk][(ty << 3) + 4];
#pragma unroll
            for (int r = 0; r < 8; r++) acc[r] += a[r] * w;
        }
        __syncthreads();
    }

    float bvv = buse[col0 + tx];
#pragma unroll
    for (int r = 0; r < 8; r++) {
        int row = (ty << 3) + r;
        float val = acc[r] + bvv;
        if (relu) val = fmaxf(val, 0.f);
        if (resid) val += resid[(size_t)row * D + col0 + tx];
        outuse[(size_t)row * ncols + col0 + tx] = val;
    }
}

// ---------------------------------------------------------------------------
// dots + softmax over the slot axis. k read as fp16.
// ---------------------------------------------------------------------------
__global__ __launch_bounds__(128) void k_dots(const float* __restrict__ q,
                                              const __half* __restrict__ kh,
                                              float* __restrict__ attn_pre) {
    int b = blockIdx.y, j0 = blockIdx.x << 7;
    int t = threadIdx.x;
    __shared__ float qs0[512], qs1[512];
    __shared__ float ks[128][65];
    {
        float4 q0 = ((const float4*)(q + (size_t)(b * 2 + 0) * D))[t];
        float4 q1 = ((const float4*)(q + (size_t)(b * 2 + 1) * D))[t];
        *(float4*)&qs0[t << 2] = q0;
        *(float4*)&qs1[t << 2] = q1;
    }
    float d0 = 0.f, d1 = 0.f;
    const __half* kb = kh + ((size_t)b * 2048 + j0) * D;
    for (int kc = 0; kc < 512; kc += 64) {
        __syncthreads();
#pragma unroll
        for (int i = 0; i < 8; i++) {
            int f = t + (i << 7);
            int j = f >> 3, hp = (f & 7) << 3;
            uint4 kv = *(const uint4*)(kb + (size_t)j * D + kc + hp);
            float2 f0 = u2f2(kv.x), f1 = u2f2(kv.y);
            float2 f2 = u2f2(kv.z), f3 = u2f2(kv.w);
            ks[j][hp + 0] = f0.x; ks[j][hp + 1] = f0.y;
            ks[j][hp + 2] = f1.x; ks[j][hp + 3] = f1.y;
            ks[j][hp + 4] = f2.x; ks[j][hp + 5] = f2.y;
            ks[j][hp + 6] = f3.x; ks[j][hp + 7] = f3.y;
        }
        __syncthreads();
#pragma unroll
        for (int kk = 0; kk < 64; kk++) {
            float kv = ks[t][kk];
            d0 += kv * qs0[kc + kk];
            d1 += kv * qs1[kc + kk];
        }
    }
    const float SC = 0.044194173824159216f;
    d0 *= SC; d1 *= SC;
    float mx = fmaxf(d0, d1);
    float e0 = expf(d0 - mx), e1 = expf(d1 - mx);
    float inv = 1.0f / (e0 + e1);
    attn_pre[b * 4096 + (j0 + t)]        = e0 * inv;
    attn_pre[b * 4096 + 2048 + (j0 + t)] = e1 * inv;
}

// ---------------------------------------------------------------------------
// k_rowsum: rowsum of attn_pre -> rinv, plus normalized attn_out.
// 64 blocks (one per b,slot) x 256.
// ---------------------------------------------------------------------------
__global__ void k_rowsum(const float* __restrict__ attn_pre,
                         float* __restrict__ attn_out,
                         float* __restrict__ rinv) {
    int r = blockIdx.x, t = threadIdx.x;
    size_t off = (size_t)(r >> 1) * 4096 + (size_t)(r & 1) * 2048;
    const float* p = attn_pre + off;
    float s = 0.f;
    for (int j = t; j < 2048; j += 256) s += p[j];
#pragma unroll
    for (int o = 16; o; o >>= 1) s += __shfl_down_sync(0xffffffffu, s, o);
    __shared__ float ss[8];
    __shared__ float sinv;
    if ((t & 31) == 0) ss[t >> 5] = s;
    __syncthreads();
    if (t == 0) {
        float S = ss[0] + ss[1] + ss[2] + ss[3] + ss[4] + ss[5] + ss[6] + ss[7];
        float inv = 1.0f / (S + 1e-8f);
        rinv[r] = inv;
        sinv = inv;
    }
    __syncthreads();
    float inv = sinv;
    float* o = attn_out + off;
    for (int j = t; j < 2048; j += 256) o[j] = p[j] * inv;
}

// ---------------------------------------------------------------------------
// k_upd_part: partial (v^T @ attn) over a 256-j chunk.
// Grid (4 d-tiles, 32 batches, 8 j-chunks) x 128.
// updp layout: [jch][b*2+slot][512].
// ---------------------------------------------------------------------------
__global__ __launch_bounds__(128) void k_upd_part(const float* __restrict__ attn_pre,
                                                  const __half* __restrict__ vh,
                                                  float* __restrict__ updp) {
    int b = blockIdx.y, d0 = blockIdx.x << 7, jch = blockIdx.z, t = threadIdx.x;
    const int j0 = jch << 8;
    const float* a0p = attn_pre + b * 4096 + j0;
    const float* a1p = a0p + 2048;
    __shared__ float w0[256], w1[256];
    w0[t] = a0p[t]; w0[t + 128] = a0p[t + 128];
    w1[t] = a1p[t]; w1[t + 128] = a1p[t + 128];
    __syncthreads();
    float acc0 = 0.f, acc1 = 0.f;
    const __half* vb = vh + ((size_t)b * 2048 + j0) * D + d0 + t;
#pragma unroll 8
    for (int jj = 0; jj < 256; jj++) {
        float vv = __half2float(vb[(size_t)jj * D]);
        acc0 += vv * w0[jj];
        acc1 += vv * w1[jj];
    }
    updp[(size_t)(jch * 64 + b * 2 + 0) * D + d0 + t] = acc0;
    updp[(size_t)(jch * 64 + b * 2 + 1) * D + d0 + t] = acc1;
}

// ---------------------------------------------------------------------------
// k_upd_red: sum 8 partials * rinv -> upd. 128 blocks x 256.
// ---------------------------------------------------------------------------
__global__ void k_upd_red(const float* __restrict__ updp,
                          const float* __restrict__ rinv,
                          float* __restrict__ upd) {
    int idx = blockIdx.x * 256 + threadIdx.x;   // 0..32767
    int row = idx >> 9;
    float s = 0.f;
#pragma unroll
    for (int p = 0; p < 8; p++) s += updp[(size_t)(p * 64 + row) * D + (idx & 511)];
    upd[idx] = s * rinv[row];
}

// ---------------------------------------------------------------------------
// Fused GRU gates + LayerNorm(h_new). 64 blocks x 128 threads.
// ---------------------------------------------------------------------------
__global__ void k_gruln(const float* __restrict__ gx, const float* __restrict__ gh,
                        const float* __restrict__ slots,
                        const float* __restrict__ g, const float* __restrict__ b,
                        float* __restrict__ hnew, float* __restrict__ hln) {
    int r = blockIdx.x, t = threadIdx.x;
    const float* gxr = gx + (size_t)r * 1536;
    const float* ghr = gh + (size_t)r * 1536;
    float4 xr = ((const float4*)(gxr))[t];
    float4 hr = ((const float4*)(ghr))[t];
    float4 xz = ((const float4*)(gxr + 512))[t];
    float4 hz = ((const float4*)(ghr + 512))[t];
    float4 xn = ((const float4*)(gxr + 1024))[t];
    float4 hn = ((const float4*)(ghr + 1024))[t];
    float4 hp = ((const float4*)(slots + (size_t)r * D))[t];

    float h[4];
    {
        float rg, z, n;
        rg = sigmoidf_(xr.x + hr.x); z = sigmoidf_(xz.x + hz.x);
        n = tanhf(xn.x + rg * hn.x); h[0] = (1.f - z) * n + z * hp.x;
        rg = sigmoidf_(xr.y + hr.y); z = sigmoidf_(xz.y + hz.y);
        n = tanhf(xn.y + rg * hn.y); h[1] = (1.f - z) * n + z * hp.y;
        rg = sigmoidf_(xr.z + hr.z); z = sigmoidf_(xz.z + hz.z);
        n = tanhf(xn.z + rg * hn.z); h[2] = (1.f - z) * n + z * hp.z;
        rg = sigmoidf_(xr.w + hr.w); z = sigmoidf_(xz.w + hz.w);
        n = tanhf(xn.w + rg * hn.w); h[3] = (1.f - z) * n + z * hp.w;
    }
    ((float4*)(hnew + (size_t)r * D))[t] = make_float4(h[0], h[1], h[2], h[3]);

    float s  = h[0] + h[1] + h[2] + h[3];
    float s2 = h[0]*h[0] + h[1]*h[1] + h[2]*h[2] + h[3]*h[3];
#pragma unroll
    for (int o = 16; o; o >>= 1) {
        s  += __shfl_down_sync(0xffffffffu, s,  o);
        s2 += __shfl_down_sync(0xffffffffu, s2, o);
    }
    __shared__ float ss[4], ss2[4];
    __shared__ float sm, srs;
    if ((t & 31) == 0) { ss[t >> 5] = s; ss2[t >> 5] = s2; }
    __syncthreads();
    if (t == 0) {
        float S  = ss[0] + ss[1] + ss[2] + ss[3];
        float S2 = ss2[0] + ss2[1] + ss2[2] + ss2[3];
        float mm  = S * (1.0f / 512.0f);
        float var = S2 * (1.0f / 512.0f) - mm * mm;
        sm = mm; srs = rsqrtf(var + 1e-5f);
    }
    __syncthreads();
    float mm = sm, rs = srs;
    float4 gg = ((const float4*)g)[t];
    float4 bb = ((const float4*)b)[t];
    float4 o;
    o.x = (h[0] - mm) * rs * gg.x + bb.x;
    o.y = (h[1] - mm) * rs * gg.y + bb.y;
    o.z = (h[2] - mm) * rs * gg.z + bb.z;
    o.w = (h[3] - mm) * rs * gg.w + bb.w;
    ((float4*)(hln + (size_t)r * D))[t] = o;
}

// ---------------------------------------------------------------------------
// host
// ---------------------------------------------------------------------------
extern "C" void kernel_launch(void* const* d_in, const int* in_sizes, int n_in,
                              void* d_out, int out_size) {
    (void)in_sizes; (void)n_in; (void)out_size;
    const float* inputs     = (const float*)d_in[0];
    const float* init_slots = (const float*)d_in[1];
    const float* Wq  = (const float*)d_in[2];
    const float* bq  = (const float*)d_in[3];
    const float* Wk  = (const float*)d_in[4];
    const float* bk  = (const float*)d_in[5];
    const float* Wv  = (const float*)d_in[6];
    const float* bv  = (const float*)d_in[7];
    const float* ln_in_g = (const float*)d_in[8];
    const float* ln_in_b = (const float*)d_in[9];
    const float* ln_s_g  = (const float*)d_in[10];
    const float* ln_s_b  = (const float*)d_in[11];
    const float* ln_f_g  = (const float*)d_in[12];
    const float* ln_f_b  = (const float*)d_in[13];
    const float* gru_wih = (const float*)d_in[14];
    const float* gru_whh = (const float*)d_in[15];
    const float* gru_bih = (const float*)d_in[16];
    const float* gru_bhh = (const float*)d_in[17];
    const float* W1 = (const float*)d_in[18];
    const float* b1 = (const float*)d_in[19];
    const float* W2 = (const float*)d_in[20];
    const float* b2 = (const float*)d_in[21];

    float* out      = (float*)d_out;
    float* slots    = out;
    float* qout     = out + 32768;
    float* kout     = out + 65536;
    float* attn_out = out + 65536 + 33554432;

    float* S = nullptr;
    cudaGetSymbolAddress((void**)&S, g_scratch);
    __half* vh  = (__half*)(S + OFF_VH);
    __half* khs = (__half*)(S + OFF_KH);
    float* attn = S + OFF_ATTN;
    float* sln  = S + OFF_SLN;
    float* upd  = S + OFF_UPD;
    float* gx   = S + OFF_GX;
    float* gh   = S + OFF_GH;
    float* hnew = S + OFF_HNEW;
    float* hln  = S + OFF_HLN;
    float* tbuf = S + OFF_T;
    __half* whi = (__half*)(S + OFF_WHI);
    __half* xh  = (__half*)(S + OFF_XH);
    float* updp = S + OFF_UPDP;
    float* rinv = S + OFF_RINV;

    cudaFuncSetAttribute(k_mmagemm, cudaFuncAttributeMaxDynamicSharedMemorySize,
                         PTOT);

    cudaMemcpyAsync(slots, init_slots, 32768 * sizeof(float),
                    cudaMemcpyDeviceToDevice);

    k_prepw<<<2048, 256>>>(Wk, Wv, whi);
    k_prepx<<<NROWS, 128>>>(inputs, ln_in_g, ln_in_b, xh);
    k_mmagemm<<<dim3(8, 512), 256, PTOT>>>(xh, whi, bk, bv, kout, khs, vh);

    for (int it = 0; it < 3; ++it) {
        k_ln64<<<64, 128>>>(slots, ln_s_g, ln_s_b, sln);
        k_gemm64<0><<<dim3(16, 1), 256>>>(sln, sln, Wq, Wq, bq, bq, nullptr,
                                          qout, qout, 512, 0);
        k_dots<<<dim3(16, 32), 128>>>(qout, khs, attn);
        k_rowsum<<<64, 256>>>(attn, attn_out, rinv);
        k_upd_part<<<dim3(4, 32, 8), 128>>>(attn, vh, updp);
        k_upd_red<<<128, 256>>>(updp, rinv, upd);
        k_gemm64<1><<<dim3(48, 2), 256>>>(upd, slots, gru_wih, gru_whh,
                                          gru_bih, gru_bhh, nullptr,
                                          gx, gh, 1536, 0);
        k_gruln<<<64, 128>>>(gx, gh, slots, ln_f_g, ln_f_b, hnew, hln);
        k_gemm64<0><<<dim3(16, 1), 256>>>(hln, hln, W1, W1, b1, b1, nullptr,
                                          tbuf, tbuf, 512, 1);
        k_gemm64<0><<<dim3(16, 1), 256>>>(tbuf, tbuf, W2, W2, b2, b2, hnew,
                                          slots, slots, 512, 0);
    }
}